// round 17
// baseline (speedup 1.0000x reference)
#include <cuda_runtime.h>
#include <cuda_bf16.h>
#include <cstdint>

// Scratch (static device globals — no allocation).
__device__ uint4 g_Tb4[8][32][1024];      // 4 MB: bf16 pose-chunk partials of T[b][g]
__device__ float g_pp[128][2048];         // 1 MB: stage2 partial pooled [slot][b*64+c]

// ---- packed f32x2 helpers ----
__device__ __forceinline__ unsigned long long pack2(float x, float y) {
    unsigned long long r;
    asm("mov.b64 %0, {%1,%2};" : "=l"(r) : "f"(x), "f"(y));
    return r;
}
__device__ __forceinline__ void fma2(unsigned long long& d, unsigned long long a, unsigned long long b) {
    asm("fma.rn.f32x2 %0, %1, %2, %0;" : "+l"(d) : "l"(a), "l"(b));
}
__device__ __forceinline__ float2 unpk(unsigned long long v) {
    float2 r;
    asm("mov.b64 {%0,%1}, %2;" : "=f"(r.x), "=f"(r.y) : "l"(v));
    return r;
}
// d[31:16] = bf16(hi), d[15:0] = bf16(lo)
__device__ __forceinline__ uint32_t bfpack(float hi, float lo) {
    uint32_t r;
    asm("cvt.rn.bf16x2.f32 %0, %1, %2;" : "=r"(r) : "f"(hi), "f"(lo));
    return r;
}

// ============================================================================
// Stage 1 (4 KB-granule streams): T[b, j*64 + r*8 + x] += (CP[b,i]@Wc[i])[r][x]
// Warp gw (2048, 1024 blocks x 2): b = gw&31, jc = (gw>>5)&7 (16 j's),
// sc = gw>>8 (8 poses). Per pose the warp walks FOUR sequential 1 KB
// sub-chunks (4 matrices each) -> 4 KB contiguous per stream before the
// +32 KB pose jump (vs 1 KB in R8; DRAM-locality lever). Inner loop is the
// validated R5/R8 core: lane l owns row r=l&7 of matrix q=l>>3; W staged in
// bank-skewed per-warp smem (stride 72), double-buffered, __syncwarp only.
// acc[t] indexed by compile-time t (inner loop fully unrolled).
// W is L2-amortized across the 32 b-warps sharing each (jc,sc) slab.
// ============================================================================
__global__ void __launch_bounds__(64) k_stage1(const float* __restrict__ cp,
                                               const float* __restrict__ wc) {
    const int tid = threadIdx.x;
    const int wip = tid >> 5;
    const int l   = tid & 31;
    const int gw  = blockIdx.x * 2 + wip;   // 0..2047
    const int b   = gw & 31;
    const int jc  = (gw >> 5) & 7;
    const int sc  = gw >> 8;                // 0..7
    const int j0  = jc * 16;
    const int p0  = sc * 8;
    const int q   = l >> 3;

    __shared__ float sW[2][2][288];   // [warp][buf][4*72]

    // STS offsets for W float4s f0=l, f1=l+32:  (f>>4)*72 + ((f&15)>>1)*8 + (f&1)*4
    const int so0 = (l >> 4) * 72 + ((l & 15) >> 1) * 8 + (l & 1) * 4;
    const int so1 = so0 + 144;

    const float4* a4 = reinterpret_cast<const float4*>(cp)
                       + ((size_t)b * 8192 + (size_t)p0 * 128 + j0) * 16;
    const float4* w4 = reinterpret_cast<const float4*>(wc)
                       + ((size_t)p0 * 128 + j0) * 16;

    float4 Apf[2][2], Wpf[2][2];
    Apf[0][0] = a4[2 * l]; Apf[0][1] = a4[2 * l + 1];
    Wpf[0][0] = w4[l];     Wpf[0][1] = w4[l + 32];

    unsigned long long acc[4][4];
#pragma unroll
    for (int t = 0; t < 4; ++t)
#pragma unroll
        for (int c = 0; c < 4; ++c) acc[t][c] = 0ull;

#pragma unroll 1
    for (int p = 0; p < 8; ++p) {
#pragma unroll
        for (int t = 0; t < 4; ++t) {
            const int cur = t & 1, nxt = cur ^ 1;   // s = 4p+t -> parity = t&1
            float* sw = sW[wip][cur];
            *reinterpret_cast<float4*>(sw + so0) = Wpf[cur][0];
            *reinterpret_cast<float4*>(sw + so1) = Wpf[cur][1];
            __syncwarp();

            if (t < 3 || p < 7) {    // prefetch next sub-chunk
                const int adv = (t < 3) ? 64 : 1856;   // +1KB, or next pose
                a4 += adv; w4 += adv;
                Apf[nxt][0] = a4[2 * l]; Apf[nxt][1] = a4[2 * l + 1];
                Wpf[nxt][0] = w4[l];     Wpf[nxt][1] = w4[l + 32];
            }

            const float4 alo = Apf[cur][0], ahi = Apf[cur][1];
            const float am[8] = {alo.x, alo.y, alo.z, alo.w,
                                 ahi.x, ahi.y, ahi.z, ahi.w};
            const float* wq = sw + q * 72;
#pragma unroll
            for (int m = 0; m < 8; ++m) {
                const ulonglong2 wlo = *reinterpret_cast<const ulonglong2*>(wq + m * 8);
                const ulonglong2 whi = *reinterpret_cast<const ulonglong2*>(wq + m * 8 + 4);
                const unsigned long long pa = pack2(am[m], am[m]);
                fma2(acc[t][0], pa, wlo.x); fma2(acc[t][1], pa, wlo.y);
                fma2(acc[t][2], pa, whi.x); fma2(acc[t][3], pa, whi.y);
            }
            __syncwarp();
        }
    }

    // Store: matrix j = j0 + 4t + q, row r=l&7 -> uint4 idx = j0*8 + 32t + l.
    // Warp covers contiguous 512 B per t -> coalesced.
#pragma unroll
    for (int t = 0; t < 4; ++t) {
        float2 v0 = unpk(acc[t][0]), v1 = unpk(acc[t][1]);
        float2 v2 = unpk(acc[t][2]), v3 = unpk(acc[t][3]);
        uint4 u;
        u.x = bfpack(v0.y, v0.x);
        u.y = bfpack(v1.y, v1.x);
        u.z = bfpack(v2.y, v2.x);
        u.w = bfpack(v3.y, v3.x);
        g_Tb4[sc][b][j0 * 8 + 32 * t + l] = u;
    }
}

// ============================================================================
// Stage 2 (proven R16 structure): fold 8 bf16 pose-chunk partials of T;
// E folded over hid%64 at load:
//   pp[b,c] += T[b,g] * (E[g][c] + E[g][c+64] + E[g][c+128] + E[g][c+192])
// 128 blocks x 256 threads; block owns 64 g; thread = (c 64, gq 4) x 16 g.
// gq-partials folded in-block through smem -> ONE g_pp slot per block.
// ============================================================================
__global__ void __launch_bounds__(256) k_stage2(const float* __restrict__ E) {
    const int blk = blockIdx.x;
    const int g0  = blk * 64;
    const int tid = threadIdx.x;
    __shared__ float sT[64][34];
    __shared__ float sF[4][2048];

    // ---- load + fold bf16 Tpart into sT[gg][b] ----
    {
        const uint32_t* tb = reinterpret_cast<const uint32_t*>(g_Tb4);
        const int gh = blk * 32;           // u32 offset within a b-row
#pragma unroll
        for (int k = 0; k < 4; ++k) {
            const int p = k * 256 + tid;   // 0..1023
            const int b = p >> 5, gp = p & 31;
            float lo = 0.f, hi = 0.f;
#pragma unroll
            for (int pc = 0; pc < 8; ++pc) {
                const uint32_t u = tb[(size_t)(pc * 32 + b) * 4096 + gh + gp];
                const __nv_bfloat162 h = *reinterpret_cast<const __nv_bfloat162*>(&u);
                lo += __low2float(h);
                hi += __high2float(h);
            }
            sT[2 * gp][b]     = lo;
            sT[2 * gp + 1][b] = hi;
        }
    }
    __syncthreads();

    const int c  = tid & 63;
    const int gq = tid >> 6;
    unsigned long long acc[16];
#pragma unroll
    for (int i = 0; i < 16; ++i) acc[i] = 0ull;

    const float* Eb = E + (size_t)g0 * 256 + c;
#pragma unroll 2
    for (int t = 0; t < 16; ++t) {
        const int gg = gq * 16 + t;
        const float* er = Eb + (size_t)gg * 256;
        const float ev = er[0] + er[64] + er[128] + er[192];
        const unsigned long long ep = pack2(ev, ev);
        const unsigned long long* t2 =
            reinterpret_cast<const unsigned long long*>(&sT[gg][0]);
#pragma unroll
        for (int bb = 0; bb < 16; ++bb) fma2(acc[bb], t2[bb], ep);
    }

    // Spill per-gq partials (lane-consecutive c -> conflict-free).
#pragma unroll
    for (int bb = 0; bb < 16; ++bb) {
        float2 v = unpk(acc[bb]);
        sF[gq][(2 * bb + 0) * 64 + c] = v.x;
        sF[gq][(2 * bb + 1) * 64 + c] = v.y;
    }
    __syncthreads();

    // Fold gq and write ONE slot for this block.
    float* dst = g_pp[blk];
#pragma unroll
    for (int k = 0; k < 8; ++k) {
        const int e = k * 256 + tid;
        dst[e] = sF[0][e] + sF[1][e] + sF[2][e] + sF[3][e];
    }
}

// ============================================================================
// Final (proven R8/R16): pooled[b,c] = (sum of 128 slots)/64 + rel[c];
//        out[b,o] = pooled(8x8) @ w_next[o].   32 blocks x 256 threads.
// ============================================================================
__global__ void __launch_bounds__(256) k_final(const float* __restrict__ wn,
                                               const float* __restrict__ rel,
                                               float* __restrict__ out) {
    const int b   = blockIdx.x;
    const int tid = threadIdx.x;
    const int c   = tid & 63, qd = tid >> 6;
    __shared__ float sN[64];
    __shared__ float sP[4][64];
    __shared__ float sWn[4096];

    float s = 0.f;
#pragma unroll 8
    for (int k = 0; k < 32; ++k) s += g_pp[qd * 32 + k][b * 64 + c];
    sP[qd][c] = s;

    {
        float4* s4 = reinterpret_cast<float4*>(sWn);
        const float4* w4 = reinterpret_cast<const float4*>(wn);
#pragma unroll
        for (int k = 0; k < 4; ++k) s4[k * 256 + tid] = w4[k * 256 + tid];
    }
    __syncthreads();
    if (tid < 64) {
        sN[tid] = (sP[0][tid] + sP[1][tid] + sP[2][tid] + sP[3][tid]) * (1.f / 64.f)
                  + rel[tid];
    }
    __syncthreads();

    const int r = c >> 3, col = c & 7;
    float a[8];
#pragma unroll
    for (int m = 0; m < 8; ++m) a[m] = sN[r * 8 + m];
    float* ob = out + (size_t)b * 4096;
#pragma unroll 4
    for (int o = qd * 16; o < qd * 16 + 16; ++o) {
        float accv = 0.f;
#pragma unroll
        for (int m = 0; m < 8; ++m) accv += a[m] * sWn[o * 64 + m * 8 + col];
        ob[o * 64 + c] = accv;
    }
}

extern "C" void kernel_launch(void* const* d_in, const int* in_sizes, int n_in,
                              void* d_out, int out_size) {
    const float* cp  = (const float*)d_in[0];  // current_pose (32,8192,64)
    const float* wc  = (const float*)d_in[1];  // w_current    (8192,8,8)
    const float* wn  = (const float*)d_in[2];  // w_next       (64,8,8)
    const float* E   = (const float*)d_in[3];  // E_proj       (32,256,256)
    const float* rel = (const float*)d_in[4];  // rel_embedd   (64)
    float* out = (float*)d_out;                // (32,64,64) fp32

    k_stage1<<<1024, 64>>>(cp, wc);
    k_stage2<<<128, 256>>>(E);
    k_final<<<32, 256>>>(wn, rel, out);
}